// round 3
// baseline (speedup 1.0000x reference)
#include <cuda_runtime.h>
#include <math.h>

// Problem constants
constexpr int BB = 8;
constexpr int TT = 2048;
constexpr int CCH = 768;   // n_embed
constexpr int HH = 256;    // head_size
constexpr int M_TOT = BB * TT;  // 16384

// Scratch for Q, K, V projections (16 MB each) — device globals, no allocation.
__device__ float g_q[M_TOT * HH];
__device__ float g_k[M_TOT * HH];
__device__ float g_v[M_TOT * HH];

// ---------------------------------------------------------------------------
// QKV projection: Out[m][n] = sum_k x[m][k] * W[k][n]
// M=16384, K=768, N=256. Tiles: BM=128, BN=64, BK=16. 256 threads, 8x4 per thread.
// blockIdx.z selects q/k/v.
// ---------------------------------------------------------------------------
__global__ __launch_bounds__(256) void qkv_kernel(
    const float* __restrict__ x,
    const float* __restrict__ Wq,
    const float* __restrict__ Wk,
    const float* __restrict__ Wv)
{
    __shared__ float As[16][129];  // [k][m], padded
    __shared__ float Bs[16][65];   // [k][n], padded

    const float* W;
    float* Out;
    if (blockIdx.z == 0)      { W = Wq; Out = g_q; }
    else if (blockIdx.z == 1) { W = Wk; Out = g_k; }
    else                      { W = Wv; Out = g_v; }

    const int bm0 = blockIdx.x * 128;
    const int bn0 = blockIdx.y * 64;
    const int tid = threadIdx.x;
    const int tx = tid & 15;   // col group
    const int ty = tid >> 4;   // row group

    float acc[8][4];
    #pragma unroll
    for (int r = 0; r < 8; r++)
        #pragma unroll
        for (int c = 0; c < 4; c++) acc[r][c] = 0.f;

    for (int k0 = 0; k0 < CCH; k0 += 16) {
        // Load A tile: 128 rows x 16 k. 2048 elems / 256 threads = 8 each.
        #pragma unroll
        for (int i = 0; i < 8; i++) {
            int e = tid + 256 * i;
            int am = e >> 4, ak = e & 15;
            As[ak][am] = x[(size_t)(bm0 + am) * CCH + (k0 + ak)];
        }
        // Load B tile: 16 k x 64 n. 1024 elems / 256 threads = 4 each.
        #pragma unroll
        for (int i = 0; i < 4; i++) {
            int e = tid + 256 * i;
            int bk = e >> 6, bn = e & 63;
            Bs[bk][bn] = W[(size_t)(k0 + bk) * HH + (bn0 + bn)];
        }
        __syncthreads();

        #pragma unroll
        for (int k = 0; k < 16; k++) {
            float a[8], bv[4];
            #pragma unroll
            for (int r = 0; r < 8; r++) a[r] = As[k][ty + 16 * r];
            #pragma unroll
            for (int c = 0; c < 4; c++) bv[c] = Bs[k][tx + 16 * c];
            #pragma unroll
            for (int r = 0; r < 8; r++)
                #pragma unroll
                for (int c = 0; c < 4; c++)
                    acc[r][c] += a[r] * bv[c];
        }
        __syncthreads();
    }

    #pragma unroll
    for (int r = 0; r < 8; r++)
        #pragma unroll
        for (int c = 0; c < 4; c++)
            Out[(size_t)(bm0 + ty + 16 * r) * HH + (bn0 + tx + 16 * c)] = acc[r][c];
}

// ---------------------------------------------------------------------------
// Flash attention (causal), fp32.
// One CTA per (batch, query tile of 64). Key tiles of 64, only jt <= qt.
// 256 threads as 16x16 grid:
//   S (64x64): thread (tr, tc) owns rows tr+16*rr (rr<4), cols tc+16*cj (cj<4)
//   O (64x256): same rows, cols tc+16*cc (cc<16)
// Smem: Q/K/V tiles [64][257] (pad -> conflict-free column reads), P [64][65].
// ---------------------------------------------------------------------------
constexpr int SD = 257;   // 256 + 1 pad
constexpr int PD = 65;    // 64 + 1 pad
constexpr int ATTN_SMEM = (3 * 64 * SD + 64 * PD) * (int)sizeof(float);  // 214016 B

__global__ __launch_bounds__(256) void attn_kernel(float* __restrict__ out)
{
    extern __shared__ float sm[];
    float* Qs = sm;                 // 64*SD
    float* Ks = Qs + 64 * SD;       // 64*SD
    float* Vs = Ks + 64 * SD;       // 64*SD
    float* Ps = Vs + 64 * SD;       // 64*PD

    const int b  = blockIdx.y;
    const int qt = (int)gridDim.x - 1 - (int)blockIdx.x;  // heavy tiles first
    const int tid = threadIdx.x;
    const int tc = tid & 15;
    const int tr = tid >> 4;
    const float scale = rsqrtf((float)CCH);  // scale uses n_embed, not head_size

    // Load Q tile (64 x 256) into smem. 16384 elems / 256 thr = 64 each.
    const float* qbase = g_q + ((size_t)b * TT + (size_t)qt * 64) * HH;
    #pragma unroll 4
    for (int i = 0; i < 64; i++) {
        int e = tid + 256 * i;
        int r = e >> 8, d = e & 255;
        Qs[r * SD + d] = qbase[r * HH + d];
    }

    float o[4][16];
    #pragma unroll
    for (int rr = 0; rr < 4; rr++)
        #pragma unroll
        for (int cc = 0; cc < 16; cc++) o[rr][cc] = 0.f;
    float mrow[4] = {-INFINITY, -INFINITY, -INFINITY, -INFINITY};
    float lrow[4] = {0.f, 0.f, 0.f, 0.f};

    for (int jt = 0; jt <= qt; jt++) {
        const float* kbase = g_k + ((size_t)b * TT + (size_t)jt * 64) * HH;
        const float* vbase = g_v + ((size_t)b * TT + (size_t)jt * 64) * HH;

        __syncthreads();  // previous iteration's Ps/Vs reads done
        #pragma unroll 4
        for (int i = 0; i < 64; i++) {
            int e = tid + 256 * i;
            int r = e >> 8, d = e & 255;
            Ks[r * SD + d] = kbase[r * HH + d];
            Vs[r * SD + d] = vbase[r * HH + d];
        }
        __syncthreads();

        // S = Q K^T for this tile: 4x4 per thread, accumulate over 256 dims.
        float s[4][4];
        #pragma unroll
        for (int rr = 0; rr < 4; rr++)
            #pragma unroll
            for (int cj = 0; cj < 4; cj++) s[rr][cj] = 0.f;

        #pragma unroll 4
        for (int d = 0; d < HH; d++) {
            float q[4], kv[4];
            #pragma unroll
            for (int rr = 0; rr < 4; rr++) q[rr] = Qs[(tr + 16 * rr) * SD + d];
            #pragma unroll
            for (int cj = 0; cj < 4; cj++) kv[cj] = Ks[(tc + 16 * cj) * SD + d];
            #pragma unroll
            for (int rr = 0; rr < 4; rr++)
                #pragma unroll
                for (int cj = 0; cj < 4; cj++)
                    s[rr][cj] += q[rr] * kv[cj];
        }

        // Online softmax per row. Lanes sharing tr (16 of them, xor-aligned
        // within the warp) each hold 4 cols of the row.
        const bool diag = (jt == qt);
        #pragma unroll
        for (int rr = 0; rr < 4; rr++) {
            const int r = tr + 16 * rr;
            const int qi = qt * 64 + r;
            float tmax = -INFINITY;
            #pragma unroll
            for (int cj = 0; cj < 4; cj++) {
                float sv = s[rr][cj] * scale;
                if (diag && (jt * 64 + tc + 16 * cj) > qi) sv = -INFINITY;
                s[rr][cj] = sv;
                tmax = fmaxf(tmax, sv);
            }
            #pragma unroll
            for (int off = 1; off < 16; off <<= 1)
                tmax = fmaxf(tmax, __shfl_xor_sync(0xffffffffu, tmax, off));

            float newm = fmaxf(mrow[rr], tmax);
            float corr = __expf(mrow[rr] - newm);  // exp(-inf)=0 on first tile
            mrow[rr] = newm;

            float ssum = 0.f;
            #pragma unroll
            for (int cj = 0; cj < 4; cj++) {
                float p = __expf(s[rr][cj] - newm);
                ssum += p;
                Ps[r * PD + tc + 16 * cj] = p;
            }
            #pragma unroll
            for (int off = 1; off < 16; off <<= 1)
                ssum += __shfl_xor_sync(0xffffffffu, ssum, off);

            lrow[rr] = lrow[rr] * corr + ssum;
            #pragma unroll
            for (int cc = 0; cc < 16; cc++) o[rr][cc] *= corr;
        }
        __syncthreads();  // Ps fully written before PV reads

        // O += P V : per kk, 4 P loads + 16 V loads -> 64 FFMA.
        #pragma unroll 2
        for (int kk = 0; kk < 64; kk++) {
            float pr[4];
            #pragma unroll
            for (int rr = 0; rr < 4; rr++) pr[rr] = Ps[(tr + 16 * rr) * PD + kk];
            #pragma unroll
            for (int cc = 0; cc < 16; cc++) {
                float v = Vs[kk * SD + tc + 16 * cc];
                #pragma unroll
                for (int rr = 0; rr < 4; rr++) o[rr][cc] += pr[rr] * v;
            }
        }
    }

    // Normalize and write out.
    #pragma unroll
    for (int rr = 0; rr < 4; rr++) {
        const int r = tr + 16 * rr;
        const float inv = 1.f / lrow[rr];
        const size_t base = ((size_t)b * TT + (size_t)qt * 64 + r) * HH;
        #pragma unroll
        for (int cc = 0; cc < 16; cc++)
            out[base + tc + 16 * cc] = o[rr][cc] * inv;
    }
}

extern "C" void kernel_launch(void* const* d_in, const int* in_sizes, int n_in,
                              void* d_out, int out_size)
{
    const float* x  = (const float*)d_in[0];
    const float* Wq = (const float*)d_in[1];
    const float* Wk = (const float*)d_in[2];
    const float* Wv = (const float*)d_in[3];
    float* out = (float*)d_out;

    cudaFuncSetAttribute(attn_kernel, cudaFuncAttributeMaxDynamicSharedMemorySize, ATTN_SMEM);

    // QKV projections: grid (M/128, N/64, 3)
    qkv_kernel<<<dim3(128, 4, 3), 256>>>(x, Wq, Wk, Wv);

    // Flash attention: grid (qtiles=32, batch=8)
    attn_kernel<<<dim3(32, 8), 256, ATTN_SMEM>>>(out);
}

// round 7
// speedup vs baseline: 3.4025x; 3.4025x over previous
#include <cuda_runtime.h>
#include <math.h>
#include <cstdint>

// Problem constants
constexpr int BB = 8;
constexpr int TT = 2048;
constexpr int CCH = 768;   // n_embed
constexpr int HH = 256;    // head_size
constexpr int M_TOT = BB * TT;  // 16384

// Device-global scratch (no allocation allowed).
__device__ float g_q[M_TOT * HH];            // [m][n] tf32-rounded
__device__ float g_k[M_TOT * HH];            // [m][n] tf32-rounded
__device__ float g_vt[BB * HH * TT];         // [b][n][t] tf32-rounded (V transposed)
__device__ float g_wt[3 * HH * CCH];         // [w][n][k] tf32-rounded (W transposed)

__device__ __forceinline__ float to_tf32(float x) {
    float y;
    asm("cvt.rna.tf32.f32 %0, %1;" : "=f"(y) : "f"(x));
    return y;
}
__device__ __forceinline__ uint32_t fbits(float f) { return __float_as_uint(f); }

// Portable warp MMA: D(16x8,f32) += A(16x8,tf32 row) * B(8x8,tf32 col)
__device__ __forceinline__ void mma_tf32(float* d, const uint32_t* a, const uint32_t* b) {
    asm volatile(
        "mma.sync.aligned.m16n8k8.row.col.f32.tf32.tf32.f32 "
        "{%0,%1,%2,%3}, {%4,%5,%6,%7}, {%8,%9}, {%0,%1,%2,%3};"
        : "+f"(d[0]), "+f"(d[1]), "+f"(d[2]), "+f"(d[3])
        : "r"(a[0]), "r"(a[1]), "r"(a[2]), "r"(a[3]), "r"(b[0]), "r"(b[1]));
}

// ---------------------------------------------------------------------------
// Weight transpose: g_wt[w][n][k] = tf32(W[k][n]).  Tiled 32x32.
// ---------------------------------------------------------------------------
__global__ void transpose_w(const float* __restrict__ Wq,
                            const float* __restrict__ Wk,
                            const float* __restrict__ Wv)
{
    __shared__ float tile[32][33];
    const float* W = (blockIdx.z == 0) ? Wq : (blockIdx.z == 1) ? Wk : Wv;
    float* Out = g_wt + (size_t)blockIdx.z * CCH * HH;
    const int k0 = blockIdx.x * 32, n0 = blockIdx.y * 32;
    const int tx = threadIdx.x, ty = threadIdx.y;
    #pragma unroll
    for (int i = 0; i < 4; i++)
        tile[ty + 8 * i][tx] = W[(size_t)(k0 + ty + 8 * i) * HH + (n0 + tx)];
    __syncthreads();
    #pragma unroll
    for (int i = 0; i < 4; i++)
        Out[(size_t)(n0 + ty + 8 * i) * CCH + (k0 + tx)] = to_tf32(tile[tx][ty + 8 * i]);
}

// ---------------------------------------------------------------------------
// QKV projection via mma.sync tf32.
// CTA tile: 128m x 128n, K chunks of 32. 8 warps as 4m x 2n; warp tile 32x64.
// grid = (M/128=128, N/128=2, 3 weights). V output written TRANSPOSED to g_vt.
// ---------------------------------------------------------------------------
constexpr int XSTR = 36;   // smem row stride (floats); bank = 4*gid + tig, conflict-free

__global__ __launch_bounds__(256) void qkv_mma(const float* __restrict__ x)
{
    __shared__ float Xs[128 * XSTR];   // [m][k]
    __shared__ float Ws[128 * XSTR];   // [n][k]

    const int tid = threadIdx.x;
    const int w = tid >> 5, lane = tid & 31;
    const int gid = lane >> 2, tig = lane & 3;
    const int wm = w & 3, wn = w >> 2;
    const int bm0 = blockIdx.x * 128, bn0 = blockIdx.y * 128;
    const int wsel = blockIdx.z;
    const float* wt = g_wt + (size_t)wsel * CCH * HH;

    float acc[2][8][4];
    #pragma unroll
    for (int mf = 0; mf < 2; mf++)
        #pragma unroll
        for (int nf = 0; nf < 8; nf++)
            #pragma unroll
            for (int j = 0; j < 4; j++) acc[mf][nf][j] = 0.f;

    for (int c = 0; c < CCH / 32; c++) {
        const int k0 = c * 32;
        // X tile: 128 x 32, float4 loads, rna->tf32.
        #pragma unroll
        for (int i = 0; i < 4; i++) {
            int e = tid + 256 * i;            // 1024 float4s
            int r = e >> 3, k4 = (e & 7) * 4;
            float4 v = *reinterpret_cast<const float4*>(&x[(size_t)(bm0 + r) * CCH + k0 + k4]);
            v.x = to_tf32(v.x); v.y = to_tf32(v.y); v.z = to_tf32(v.z); v.w = to_tf32(v.w);
            *reinterpret_cast<float4*>(&Xs[r * XSTR + k4]) = v;
        }
        // W tile: 128 n-rows x 32 k (already tf32).
        #pragma unroll
        for (int i = 0; i < 4; i++) {
            int e = tid + 256 * i;
            int r = e >> 3, k4 = (e & 7) * 4;
            *reinterpret_cast<float4*>(&Ws[r * XSTR + k4]) =
                *reinterpret_cast<const float4*>(&wt[(size_t)(bn0 + r) * CCH + k0 + k4]);
        }
        __syncthreads();

        #pragma unroll
        for (int ks = 0; ks < 4; ks++) {
            const int kb = 8 * ks;
            uint32_t a[2][4];
            #pragma unroll
            for (int mf = 0; mf < 2; mf++) {
                const int r0 = 32 * wm + 16 * mf + gid;
                a[mf][0] = fbits(Xs[r0 * XSTR + kb + tig]);
                a[mf][1] = fbits(Xs[(r0 + 8) * XSTR + kb + tig]);
                a[mf][2] = fbits(Xs[r0 * XSTR + kb + tig + 4]);
                a[mf][3] = fbits(Xs[(r0 + 8) * XSTR + kb + tig + 4]);
            }
            #pragma unroll
            for (int nf = 0; nf < 8; nf++) {
                const int nr = 64 * wn + 8 * nf + gid;
                uint32_t b[2] = { fbits(Ws[nr * XSTR + kb + tig]),
                                  fbits(Ws[nr * XSTR + kb + tig + 4]) };
                mma_tf32(acc[0][nf], a[0], b);
                mma_tf32(acc[1][nf], a[1], b);
            }
        }
        __syncthreads();
    }

    // Epilogue (outputs tf32-rounded for downstream mma consumption).
    if (wsel < 2) {
        float* Out = (wsel == 0) ? g_q : g_k;
        #pragma unroll
        for (int mf = 0; mf < 2; mf++)
            #pragma unroll
            for (int nf = 0; nf < 8; nf++) {
                const int row = bm0 + 32 * wm + 16 * mf + gid;
                const int col = bn0 + 64 * wn + 8 * nf + 2 * tig;
                float2 v0 = make_float2(to_tf32(acc[mf][nf][0]), to_tf32(acc[mf][nf][1]));
                float2 v1 = make_float2(to_tf32(acc[mf][nf][2]), to_tf32(acc[mf][nf][3]));
                *reinterpret_cast<float2*>(&Out[(size_t)row * HH + col]) = v0;
                *reinterpret_cast<float2*>(&Out[(size_t)(row + 8) * HH + col]) = v1;
            }
    } else {
        // V: write transposed g_vt[b][n][t]
        #pragma unroll
        for (int mf = 0; mf < 2; mf++)
            #pragma unroll
            for (int nf = 0; nf < 8; nf++) {
                const int col = bn0 + 64 * wn + 8 * nf + 2 * tig;
                #pragma unroll
                for (int h = 0; h < 2; h++) {
                    const int m = bm0 + 32 * wm + 16 * mf + gid + 8 * h;
                    const int bb = m >> 11, t = m & 2047;
                    g_vt[((size_t)bb * HH + col) * TT + t]       = to_tf32(acc[mf][nf][2 * h]);
                    g_vt[((size_t)bb * HH + col + 1) * TT + t]   = to_tf32(acc[mf][nf][2 * h + 1]);
                }
            }
    }
}

// ---------------------------------------------------------------------------
// Flash attention (causal) via mma.sync tf32.
// CTA: 64 queries, 256 threads (8 warps).
//   S (64x64): warps 4m x 2n, warp tile 16x32.  PV: warps 4m x 2n, tile 16x128.
// Smem: Qs/Ks [64][260], Vt [256][68], Ps [64][68], reductions.
// ---------------------------------------------------------------------------
constexpr int QKS = 260;   // bank = 4*gid + tig, conflict-free frag loads
constexpr int VTS = 68;
constexpr int OFF_QS = 0;
constexpr int OFF_KS = OFF_QS + 64 * QKS;
constexpr int OFF_VT = OFF_KS + 64 * QKS;
constexpr int OFF_PS = OFF_VT + 256 * VTS;
constexpr int OFF_PM = OFF_PS + 64 * VTS;
constexpr int OFF_SUM = OFF_PM + 256;
constexpr int OFF_NM = OFF_SUM + 256;
constexpr int OFF_CR = OFF_NM + 64;
constexpr int OFF_LI = OFF_CR + 64;
constexpr int ATTN_SMEM = (OFF_LI + 64) * (int)sizeof(float);   // 222,976 B

__global__ __launch_bounds__(256) void attn_mma(float* __restrict__ out)
{
    extern __shared__ float sm[];
    float* Qs = sm + OFF_QS;
    float* Ks = sm + OFF_KS;
    float* Vt = sm + OFF_VT;
    float* Ps = sm + OFF_PS;
    float* pm = sm + OFF_PM;
    float* psum = sm + OFF_SUM;
    float* snewm = sm + OFF_NM;
    float* scorr = sm + OFF_CR;
    float* slinv = sm + OFF_LI;

    const int b = blockIdx.y;
    const int qt = (int)gridDim.x - 1 - (int)blockIdx.x;   // heavy tiles first
    const int tid = threadIdx.x;
    const int w = tid >> 5, lane = tid & 31;
    const int gid = lane >> 2, tig = lane & 3;
    const int wm = w & 3, wn = w >> 2;
    const int m0 = 16 * wm;
    const int srow = tid & 63, sq4 = tid >> 6;   // softmax: quarter-row per thread
    const float scale = rsqrtf((float)CCH);

    // Load Q tile (64 x 256).
    #pragma unroll
    for (int i = 0; i < 16; i++) {
        int e = tid + 256 * i;
        int r = e >> 6, d4 = (e & 63) * 4;
        *reinterpret_cast<float4*>(&Qs[r * QKS + d4]) =
            *reinterpret_cast<const float4*>(&g_q[((size_t)b * TT + qt * 64 + r) * HH + d4]);
    }

    float o[16][4];
    #pragma unroll
    for (int nf = 0; nf < 16; nf++)
        #pragma unroll
        for (int j = 0; j < 4; j++) o[nf][j] = 0.f;
    float mreg = -INFINITY, lreg = 0.f;   // valid for tid < 64

    for (int jt = 0; jt <= qt; jt++) {
        __syncthreads();   // prior PV reads of Ks/Vt/Ps complete
        #pragma unroll
        for (int i = 0; i < 16; i++) {
            int e = tid + 256 * i;
            int r = e >> 6, d4 = (e & 63) * 4;
            *reinterpret_cast<float4*>(&Ks[r * QKS + d4]) =
                *reinterpret_cast<const float4*>(&g_k[((size_t)b * TT + jt * 64 + r) * HH + d4]);
        }
        #pragma unroll
        for (int i = 0; i < 16; i++) {
            int e = tid + 256 * i;
            int d = e >> 4, k4 = (e & 15) * 4;
            *reinterpret_cast<float4*>(&Vt[d * VTS + k4]) =
                *reinterpret_cast<const float4*>(&g_vt[((size_t)b * HH + d) * TT + jt * 64 + k4]);
        }
        __syncthreads();

        // ---- S = Q K^T (warp tile 16 x 32) ----
        float sacc[4][4];
        #pragma unroll
        for (int nf = 0; nf < 4; nf++)
            #pragma unroll
            for (int j = 0; j < 4; j++) sacc[nf][j] = 0.f;

        const int n0s = 32 * wn;
        #pragma unroll 4
        for (int ks = 0; ks < 32; ks++) {
            const int kb = 8 * ks;
            uint32_t a[4];
            a[0] = fbits(Qs[(m0 + gid) * QKS + kb + tig]);
            a[1] = fbits(Qs[(m0 + gid + 8) * QKS + kb + tig]);
            a[2] = fbits(Qs[(m0 + gid) * QKS + kb + tig + 4]);
            a[3] = fbits(Qs[(m0 + gid + 8) * QKS + kb + tig + 4]);
            #pragma unroll
            for (int nf = 0; nf < 4; nf++) {
                const int nr = n0s + 8 * nf + gid;
                uint32_t bb[2] = { fbits(Ks[nr * QKS + kb + tig]),
                                   fbits(Ks[nr * QKS + kb + tig + 4]) };
                mma_tf32(sacc[nf], a, bb);
            }
        }
        // store scaled S to Ps
        #pragma unroll
        for (int nf = 0; nf < 4; nf++) {
            const int r0 = m0 + gid, cc = n0s + 8 * nf + 2 * tig;
            *reinterpret_cast<float2*>(&Ps[r0 * VTS + cc]) =
                make_float2(sacc[nf][0] * scale, sacc[nf][1] * scale);
            *reinterpret_cast<float2*>(&Ps[(r0 + 8) * VTS + cc]) =
                make_float2(sacc[nf][2] * scale, sacc[nf][3] * scale);
        }
        __syncthreads();

        // ---- online softmax, 2 passes ----
        const bool dtile = (jt == qt);
        const int c0 = sq4 * 16;
        {
            float pmax = -INFINITY;
            #pragma unroll
            for (int j = 0; j < 16; j++) {
                const int c = c0 + j;
                float v = Ps[srow * VTS + c];
                if (dtile && c > srow) v = -INFINITY;
                pmax = fmaxf(pmax, v);
            }
            pm[sq4 * 64 + srow] = pmax;
        }
        __syncthreads();
        if (tid < 64) {
            float mt = fmaxf(fmaxf(pm[srow], pm[64 + srow]),
                             fmaxf(pm[128 + srow], pm[192 + srow]));
            float nm = fmaxf(mreg, mt);
            float cr = __expf(mreg - nm);
            mreg = nm;
            snewm[srow] = nm;
            scorr[srow] = cr;
        }
        __syncthreads();
        {
            const float nm = snewm[srow];
            float s = 0.f;
            #pragma unroll
            for (int j = 0; j < 16; j++) {
                const int c = c0 + j;
                float p;
                if (dtile && c > srow) p = 0.f;
                else { p = __expf(Ps[srow * VTS + c] - nm); s += p; }
                Ps[srow * VTS + c] = to_tf32(p);
            }
            psum[sq4 * 64 + srow] = s;
        }
        __syncthreads();
        if (tid < 64) {
            float ss = psum[srow] + psum[64 + srow] + psum[128 + srow] + psum[192 + srow];
            lreg = lreg * scorr[srow] + ss;
        }

        // ---- rescale O, then O += P V (warp tile 16 x 128) ----
        {
            const float cr0 = scorr[m0 + gid], cr1 = scorr[m0 + gid + 8];
            #pragma unroll
            for (int nf = 0; nf < 16; nf++) {
                o[nf][0] *= cr0; o[nf][1] *= cr0;
                o[nf][2] *= cr1; o[nf][3] *= cr1;
            }
        }
        const int n0o = 128 * wn;
        #pragma unroll
        for (int ks = 0; ks < 8; ks++) {
            const int kb = 8 * ks;
            uint32_t a[4];
            a[0] = fbits(Ps[(m0 + gid) * VTS + kb + tig]);
            a[1] = fbits(Ps[(m0 + gid + 8) * VTS + kb + tig]);
            a[2] = fbits(Ps[(m0 + gid) * VTS + kb + tig + 4]);
            a[3] = fbits(Ps[(m0 + gid + 8) * VTS + kb + tig + 4]);
            #pragma unroll
            for (int nf = 0; nf < 16; nf++) {
                const int nr = n0o + 8 * nf + gid;
                uint32_t bb[2] = { fbits(Vt[nr * VTS + kb + tig]),
                                   fbits(Vt[nr * VTS + kb + tig + 4]) };
                mma_tf32(o[nf], a, bb);
            }
        }
    }

    __syncthreads();
    if (tid < 64) slinv[srow] = 1.f / lreg;
    __syncthreads();

    const float i0 = slinv[m0 + gid], i1 = slinv[m0 + gid + 8];
    const int n0o = 128 * wn;
    #pragma unroll
    for (int nf = 0; nf < 16; nf++) {
        const int row = qt * 64 + m0 + gid;
        const int col = n0o + 8 * nf + 2 * tig;
        const size_t b0 = ((size_t)b * TT + row) * HH + col;
        const size_t b1 = ((size_t)b * TT + row + 8) * HH + col;
        *reinterpret_cast<float2*>(&out[b0]) = make_float2(o[nf][0] * i0, o[nf][1] * i0);
        *reinterpret_cast<float2*>(&out[b1]) = make_float2(o[nf][2] * i1, o[nf][3] * i1);
    }
}

extern "C" void kernel_launch(void* const* d_in, const int* in_sizes, int n_in,
                              void* d_out, int out_size)
{
    const float* x  = (const float*)d_in[0];
    const float* Wq = (const float*)d_in[1];
    const float* Wk = (const float*)d_in[2];
    const float* Wv = (const float*)d_in[3];
    float* out = (float*)d_out;

    cudaFuncSetAttribute(attn_mma, cudaFuncAttributeMaxDynamicSharedMemorySize, ATTN_SMEM);

    transpose_w<<<dim3(CCH / 32, HH / 32, 3), dim3(32, 8)>>>(Wq, Wk, Wv);
    qkv_mma<<<dim3(M_TOT / 128, HH / 128, 3), 256>>>(x);
    attn_mma<<<dim3(TT / 64, BB), 256, ATTN_SMEM>>>(out);
}

// round 10
// speedup vs baseline: 4.4009x; 1.2934x over previous
#include <cuda_runtime.h>
#include <math.h>
#include <cstdint>

// Problem constants
constexpr int BB = 8;
constexpr int TT = 2048;
constexpr int CCH = 768;   // n_embed
constexpr int HH = 256;    // head_size
constexpr int M_TOT = BB * TT;  // 16384

// Device-global scratch (no allocation allowed).
__device__ float g_q[M_TOT * HH];            // [m][n] tf32-rounded
__device__ float g_k[M_TOT * HH];            // [m][n] tf32-rounded
__device__ float g_vt[BB * HH * TT];         // [b][n][t] tf32-rounded (V transposed)
__device__ float g_wt[3 * HH * CCH];         // [w][n][k] tf32-rounded (W transposed)

__device__ __forceinline__ float to_tf32(float x) {
    float y;
    asm("cvt.rna.tf32.f32 %0, %1;" : "=f"(y) : "f"(x));
    return y;
}
__device__ __forceinline__ uint32_t fbits(float f) { return __float_as_uint(f); }
__device__ __forceinline__ uint32_t smem_u32(const void* p) {
    uint32_t a;
    asm("{ .reg .u64 t; cvta.to.shared.u64 t, %1; cvt.u32.u64 %0, t; }" : "=r"(a) : "l"(p));
    return a;
}
// Async 16B copy gmem->smem (portable sm_80+; SASS LDGSTS)
__device__ __forceinline__ void cp16(uint32_t dst, const void* src) {
    asm volatile("cp.async.cg.shared.global [%0], [%1], 16;" :: "r"(dst), "l"(src));
}
#define CP_COMMIT() asm volatile("cp.async.commit_group;" ::: "memory")
#define CP_WAIT(N)  asm volatile("cp.async.wait_group %0;" :: "n"(N) : "memory")

// Portable warp MMA: D(16x8,f32) += A(16x8,tf32 row) * B(8x8,tf32 col)
__device__ __forceinline__ void mma_tf32(float* d, const uint32_t* a, const uint32_t* b) {
    asm volatile(
        "mma.sync.aligned.m16n8k8.row.col.f32.tf32.tf32.f32 "
        "{%0,%1,%2,%3}, {%4,%5,%6,%7}, {%8,%9}, {%0,%1,%2,%3};"
        : "+f"(d[0]), "+f"(d[1]), "+f"(d[2]), "+f"(d[3])
        : "r"(a[0]), "r"(a[1]), "r"(a[2]), "r"(a[3]), "r"(b[0]), "r"(b[1]));
}

// ---------------------------------------------------------------------------
// Weight transpose: g_wt[w][n][k] = tf32(W[k][n]).  Tiled 32x32.
// ---------------------------------------------------------------------------
__global__ void transpose_w(const float* __restrict__ Wq,
                            const float* __restrict__ Wk,
                            const float* __restrict__ Wv)
{
    __shared__ float tile[32][33];
    const float* W = (blockIdx.z == 0) ? Wq : (blockIdx.z == 1) ? Wk : Wv;
    float* Out = g_wt + (size_t)blockIdx.z * CCH * HH;
    const int k0 = blockIdx.x * 32, n0 = blockIdx.y * 32;
    const int tx = threadIdx.x, ty = threadIdx.y;
    #pragma unroll
    for (int i = 0; i < 4; i++)
        tile[ty + 8 * i][tx] = W[(size_t)(k0 + ty + 8 * i) * HH + (n0 + tx)];
    __syncthreads();
    #pragma unroll
    for (int i = 0; i < 4; i++)
        Out[(size_t)(n0 + ty + 8 * i) * CCH + (k0 + tx)] = to_tf32(tile[tx][ty + 8 * i]);
}

// ---------------------------------------------------------------------------
// QKV projection via mma.sync tf32.
// CTA tile: 128m x 128n, K chunks of 32. 8 warps as 4m x 2n; warp tile 32x64.
// launch_bounds(256,2): cap regs at 128 -> 2 CTAs/SM (latency hiding).
// ---------------------------------------------------------------------------
constexpr int XSTR = 36;   // smem row stride; bank = 4*gid + tig, conflict-free

__global__ __launch_bounds__(256, 2) void qkv_mma(const float* __restrict__ x)
{
    __shared__ float Xs[128 * XSTR];   // [m][k]
    __shared__ float Ws[128 * XSTR];   // [n][k]

    const int tid = threadIdx.x;
    const int w = tid >> 5, lane = tid & 31;
    const int gid = lane >> 2, tig = lane & 3;
    const int wm = w & 3, wn = w >> 2;
    const int bm0 = blockIdx.x * 128, bn0 = blockIdx.y * 128;
    const int wsel = blockIdx.z;
    const float* wt = g_wt + (size_t)wsel * CCH * HH;

    float acc[2][8][4];
    #pragma unroll
    for (int mf = 0; mf < 2; mf++)
        #pragma unroll
        for (int nf = 0; nf < 8; nf++)
            #pragma unroll
            for (int j = 0; j < 4; j++) acc[mf][nf][j] = 0.f;

    for (int c = 0; c < CCH / 32; c++) {
        const int k0 = c * 32;
        #pragma unroll
        for (int i = 0; i < 4; i++) {
            int e = tid + 256 * i;
            int r = e >> 3, k4 = (e & 7) * 4;
            float4 v = *reinterpret_cast<const float4*>(&x[(size_t)(bm0 + r) * CCH + k0 + k4]);
            v.x = to_tf32(v.x); v.y = to_tf32(v.y); v.z = to_tf32(v.z); v.w = to_tf32(v.w);
            *reinterpret_cast<float4*>(&Xs[r * XSTR + k4]) = v;
        }
        #pragma unroll
        for (int i = 0; i < 4; i++) {
            int e = tid + 256 * i;
            int r = e >> 3, k4 = (e & 7) * 4;
            *reinterpret_cast<float4*>(&Ws[r * XSTR + k4]) =
                *reinterpret_cast<const float4*>(&wt[(size_t)(bn0 + r) * CCH + k0 + k4]);
        }
        __syncthreads();

        #pragma unroll
        for (int ks = 0; ks < 4; ks++) {
            const int kb = 8 * ks;
            uint32_t a[2][4];
            #pragma unroll
            for (int mf = 0; mf < 2; mf++) {
                const int r0 = 32 * wm + 16 * mf + gid;
                a[mf][0] = fbits(Xs[r0 * XSTR + kb + tig]);
                a[mf][1] = fbits(Xs[(r0 + 8) * XSTR + kb + tig]);
                a[mf][2] = fbits(Xs[r0 * XSTR + kb + tig + 4]);
                a[mf][3] = fbits(Xs[(r0 + 8) * XSTR + kb + tig + 4]);
            }
            #pragma unroll
            for (int nf = 0; nf < 8; nf++) {
                const int nr = 64 * wn + 8 * nf + gid;
                uint32_t b[2] = { fbits(Ws[nr * XSTR + kb + tig]),
                                  fbits(Ws[nr * XSTR + kb + tig + 4]) };
                mma_tf32(acc[0][nf], a[0], b);
                mma_tf32(acc[1][nf], a[1], b);
            }
        }
        __syncthreads();
    }

    if (wsel < 2) {
        float* Out = (wsel == 0) ? g_q : g_k;
        #pragma unroll
        for (int mf = 0; mf < 2; mf++)
            #pragma unroll
            for (int nf = 0; nf < 8; nf++) {
                const int row = bm0 + 32 * wm + 16 * mf + gid;
                const int col = bn0 + 64 * wn + 8 * nf + 2 * tig;
                float2 v0 = make_float2(to_tf32(acc[mf][nf][0]), to_tf32(acc[mf][nf][1]));
                float2 v1 = make_float2(to_tf32(acc[mf][nf][2]), to_tf32(acc[mf][nf][3]));
                *reinterpret_cast<float2*>(&Out[(size_t)row * HH + col]) = v0;
                *reinterpret_cast<float2*>(&Out[(size_t)(row + 8) * HH + col]) = v1;
            }
    } else {
        #pragma unroll
        for (int mf = 0; mf < 2; mf++)
            #pragma unroll
            for (int nf = 0; nf < 8; nf++) {
                const int col = bn0 + 64 * wn + 8 * nf + 2 * tig;
                #pragma unroll
                for (int h = 0; h < 2; h++) {
                    const int m = bm0 + 32 * wm + 16 * mf + gid + 8 * h;
                    const int bb = m >> 11, t = m & 2047;
                    g_vt[((size_t)bb * HH + col) * TT + t]     = to_tf32(acc[mf][nf][2 * h]);
                    g_vt[((size_t)bb * HH + col + 1) * TT + t] = to_tf32(acc[mf][nf][2 * h + 1]);
                }
            }
    }
}

// ---------------------------------------------------------------------------
// Flash attention (causal) via mma.sync tf32 + cp.async pipelining.
// CTA: 64 queries, 256 threads (8 warps, 4m x 2n).
// Per iter: wait K -> issue V(jt) -> S-mma -> reg softmax (shfl + 128-float
// cross-warp exchange) -> prefetch K(jt+1) -> exp/P write -> wait V -> PV.
// ---------------------------------------------------------------------------
constexpr int QKS = 260;   // Q/K row stride: bank = 4*gid + tig, conflict-free
constexpr int VTS = 68;    // Vt/Ps row stride
constexpr int OFF_QS = 0;
constexpr int OFF_KS = OFF_QS + 64 * QKS;       // 16640
constexpr int OFF_VT = OFF_KS + 64 * QKS;       // 33280
constexpr int OFF_PS = OFF_VT + 256 * VTS;      // 50688
constexpr int OFF_PM = OFF_PS + 64 * VTS;       // 55040  (pm[2][64])
constexpr int OFF_S2 = OFF_PM + 128;            // 55168  (ps2[2][64])
constexpr int ATTN_SMEM = (OFF_S2 + 128) * (int)sizeof(float);   // 221184 B

__global__ __launch_bounds__(256) void attn_mma(float* __restrict__ out)
{
    extern __shared__ float sm[];
    float* Qs = sm + OFF_QS;
    float* Ks = sm + OFF_KS;
    float* Vt = sm + OFF_VT;
    float* Ps = sm + OFF_PS;
    float* pm = sm + OFF_PM;
    float* ps2 = sm + OFF_S2;

    const uint32_t sb = smem_u32(sm);
    const uint32_t uQs = sb + OFF_QS * 4, uKs = sb + OFF_KS * 4, uVt = sb + OFF_VT * 4;

    const int b = blockIdx.y;
    const int qt = (int)gridDim.x - 1 - (int)blockIdx.x;   // heavy tiles first
    const int tid = threadIdx.x;
    const int w = tid >> 5, lane = tid & 31;
    const int gid = lane >> 2, tig = lane & 3;
    const int wm = w & 3, wn = w >> 2;
    const int m0 = 16 * wm;
    const int r0 = m0 + gid, r1 = r0 + 8;
    const float scale = rsqrtf((float)CCH);

    // Prologue: async-load Q tile and K(0).
    #pragma unroll
    for (int i = 0; i < 16; i++) {
        int e = tid + 256 * i;
        int r = e >> 6, d4 = (e & 63) * 4;
        cp16(uQs + (r * QKS + d4) * 4, &g_q[((size_t)b * TT + qt * 64 + r) * HH + d4]);
    }
    CP_COMMIT();
    #pragma unroll
    for (int i = 0; i < 16; i++) {
        int e = tid + 256 * i;
        int r = e >> 6, d4 = (e & 63) * 4;
        cp16(uKs + (r * QKS + d4) * 4, &g_k[((size_t)b * TT + r) * HH + d4]);
    }
    CP_COMMIT();

    float o[16][4];
    #pragma unroll
    for (int nf = 0; nf < 16; nf++)
        #pragma unroll
        for (int j = 0; j < 4; j++) o[nf][j] = 0.f;
    float m0r = -INFINITY, m1r = -INFINITY, l0r = 0.f, l1r = 0.f;

    for (int jt = 0; jt <= qt; jt++) {
        // All pending (K(jt), and at jt=0 also Q) complete; barrier for visibility
        // and to ensure prior PV readers are done with Vt/Ps before overwrite.
        CP_WAIT(0);
        __syncthreads();

        // Issue V(jt) async — hidden behind S-mma + softmax.
        #pragma unroll
        for (int i = 0; i < 16; i++) {
            int e = tid + 256 * i;
            int d = e >> 4, k4 = (e & 15) * 4;
            cp16(uVt + (d * VTS + k4) * 4, &g_vt[((size_t)b * HH + d) * TT + jt * 64 + k4]);
        }
        CP_COMMIT();

        // ---- S = Q K^T (warp tile 16 x 32) ----
        float sacc[4][4];
        #pragma unroll
        for (int nf = 0; nf < 4; nf++)
            #pragma unroll
            for (int j = 0; j < 4; j++) sacc[nf][j] = 0.f;

        const int n0s = 32 * wn;
        #pragma unroll 4
        for (int ks = 0; ks < 32; ks++) {
            const int kb = 8 * ks;
            uint32_t a[4];
            a[0] = fbits(Qs[r0 * QKS + kb + tig]);
            a[1] = fbits(Qs[r1 * QKS + kb + tig]);
            a[2] = fbits(Qs[r0 * QKS + kb + tig + 4]);
            a[3] = fbits(Qs[r1 * QKS + kb + tig + 4]);
            #pragma unroll
            for (int nf = 0; nf < 4; nf++) {
                const int nr = n0s + 8 * nf + gid;
                uint32_t bb[2] = { fbits(Ks[nr * QKS + kb + tig]),
                                   fbits(Ks[nr * QKS + kb + tig + 4]) };
                mma_tf32(sacc[nf], a, bb);
            }
        }

        // ---- register softmax: scale, mask, partial row max ----
        const bool dtile = (jt == qt);
        float mx0 = -INFINITY, mx1 = -INFINITY;
        #pragma unroll
        for (int nf = 0; nf < 4; nf++) {
            const int c0 = n0s + 8 * nf + 2 * tig;
            float v00 = sacc[nf][0] * scale, v01 = sacc[nf][1] * scale;
            float v10 = sacc[nf][2] * scale, v11 = sacc[nf][3] * scale;
            if (dtile) {
                if (c0 > r0)     v00 = -INFINITY;
                if (c0 + 1 > r0) v01 = -INFINITY;
                if (c0 > r1)     v10 = -INFINITY;
                if (c0 + 1 > r1) v11 = -INFINITY;
            }
            sacc[nf][0] = v00; sacc[nf][1] = v01; sacc[nf][2] = v10; sacc[nf][3] = v11;
            mx0 = fmaxf(mx0, fmaxf(v00, v01));
            mx1 = fmaxf(mx1, fmaxf(v10, v11));
        }
        mx0 = fmaxf(mx0, __shfl_xor_sync(0xffffffffu, mx0, 1));
        mx0 = fmaxf(mx0, __shfl_xor_sync(0xffffffffu, mx0, 2));
        mx1 = fmaxf(mx1, __shfl_xor_sync(0xffffffffu, mx1, 1));
        mx1 = fmaxf(mx1, __shfl_xor_sync(0xffffffffu, mx1, 2));
        if (tig == 0) { pm[wn * 64 + r0] = mx0; pm[wn * 64 + r1] = mx1; }
        __syncthreads();   // pm visible; Ks reads done

        // Prefetch K(jt+1) — hidden behind exp + PV.
        {
            const int jn = (jt < qt) ? jt + 1 : jt;
            #pragma unroll
            for (int i = 0; i < 16; i++) {
                int e = tid + 256 * i;
                int r = e >> 6, d4 = (e & 63) * 4;
                cp16(uKs + (r * QKS + d4) * 4,
                     &g_k[((size_t)b * TT + jn * 64 + r) * HH + d4]);
            }
            CP_COMMIT();
        }

        // ---- combine max, exp, partial sums, write P ----
        const float nm0 = fmaxf(m0r, fmaxf(pm[r0], pm[64 + r0]));
        const float nm1 = fmaxf(m1r, fmaxf(pm[r1], pm[64 + r1]));
        const float cr0 = __expf(m0r - nm0);
        const float cr1 = __expf(m1r - nm1);
        m0r = nm0; m1r = nm1;

        float s0 = 0.f, s1 = 0.f;
        #pragma unroll
        for (int nf = 0; nf < 4; nf++) {
            const int c0 = n0s + 8 * nf + 2 * tig;
            float p00 = __expf(sacc[nf][0] - nm0);
            float p01 = __expf(sacc[nf][1] - nm0);
            float p10 = __expf(sacc[nf][2] - nm1);
            float p11 = __expf(sacc[nf][3] - nm1);
            s0 += p00 + p01;
            s1 += p10 + p11;
            *reinterpret_cast<float2*>(&Ps[r0 * VTS + c0]) =
                make_float2(to_tf32(p00), to_tf32(p01));
            *reinterpret_cast<float2*>(&Ps[r1 * VTS + c0]) =
                make_float2(to_tf32(p10), to_tf32(p11));
        }
        s0 += __shfl_xor_sync(0xffffffffu, s0, 1);
        s0 += __shfl_xor_sync(0xffffffffu, s0, 2);
        s1 += __shfl_xor_sync(0xffffffffu, s1, 1);
        s1 += __shfl_xor_sync(0xffffffffu, s1, 2);
        if (tig == 0) { ps2[wn * 64 + r0] = s0; ps2[wn * 64 + r1] = s1; }

        CP_WAIT(1);        // V(jt) landed (K(jt+1) may still fly)
        __syncthreads();   // Ps/ps2 visible; V visible

        l0r = l0r * cr0 + ps2[r0] + ps2[64 + r0];
        l1r = l1r * cr1 + ps2[r1] + ps2[64 + r1];

        // ---- rescale O, then O += P V (warp tile 16 x 128) ----
        #pragma unroll
        for (int nf = 0; nf < 16; nf++) {
            o[nf][0] *= cr0; o[nf][1] *= cr0;
            o[nf][2] *= cr1; o[nf][3] *= cr1;
        }
        const int n0o = 128 * wn;
        #pragma unroll
        for (int ks = 0; ks < 8; ks++) {
            const int kb = 8 * ks;
            uint32_t a[4];
            a[0] = fbits(Ps[r0 * VTS + kb + tig]);
            a[1] = fbits(Ps[r1 * VTS + kb + tig]);
            a[2] = fbits(Ps[r0 * VTS + kb + tig + 4]);
            a[3] = fbits(Ps[r1 * VTS + kb + tig + 4]);
            #pragma unroll
            for (int nf = 0; nf < 16; nf++) {
                const int nr = n0o + 8 * nf + gid;
                uint32_t bb[2] = { fbits(Vt[nr * VTS + kb + tig]),
                                   fbits(Vt[nr * VTS + kb + tig + 4]) };
                mma_tf32(o[nf], a, bb);
            }
        }
    }
    CP_WAIT(0);   // drain dangling K prefetch before exit

    const float i0 = 1.f / l0r, i1 = 1.f / l1r;
    const int n0o = 128 * wn;
    #pragma unroll
    for (int nf = 0; nf < 16; nf++) {
        const int row = qt * 64 + r0;
        const int col = n0o + 8 * nf + 2 * tig;
        const size_t b0 = ((size_t)b * TT + row) * HH + col;
        const size_t b1 = ((size_t)b * TT + row + 8) * HH + col;
        *reinterpret_cast<float2*>(&out[b0]) = make_float2(o[nf][0] * i0, o[nf][1] * i0);
        *reinterpret_cast<float2*>(&out[b1]) = make_float2(o[nf][2] * i1, o[nf][3] * i1);
    }
}

extern "C" void kernel_launch(void* const* d_in, const int* in_sizes, int n_in,
                              void* d_out, int out_size)
{
    const float* x  = (const float*)d_in[0];
    const float* Wq = (const float*)d_in[1];
    const float* Wk = (const float*)d_in[2];
    const float* Wv = (const float*)d_in[3];
    float* out = (float*)d_out;

    cudaFuncSetAttribute(attn_mma, cudaFuncAttributeMaxDynamicSharedMemorySize, ATTN_SMEM);

    transpose_w<<<dim3(CCH / 32, HH / 32, 3), dim3(32, 8)>>>(Wq, Wk, Wv);
    qkv_mma<<<dim3(M_TOT / 128, HH / 128, 3), 256>>>(x);
    attn_mma<<<dim3(TT / 64, BB), 256, ATTN_SMEM>>>(out);
}

// round 11
// speedup vs baseline: 5.1540x; 1.1711x over previous
#include <cuda_runtime.h>
#include <math.h>
#include <cstdint>

// Problem constants
constexpr int BB = 8;
constexpr int TT = 2048;
constexpr int CCH = 768;   // n_embed
constexpr int HH = 256;    // head_size
constexpr int M_TOT = BB * TT;  // 16384

// Device-global scratch (no allocation allowed).
__device__ float g_xr[M_TOT * CCH];          // x, tf32-rounded (rna)
__device__ float g_q[M_TOT * HH];            // [m][n] tf32-rounded
__device__ float g_k[M_TOT * HH];            // [m][n] tf32-rounded
__device__ float g_vt[BB * HH * TT];         // [b][n][t] tf32-rounded (V transposed)
__device__ float g_wt[3 * HH * CCH];         // [w][n][k] tf32-rounded (W transposed)

__device__ __forceinline__ float to_tf32(float x) {
    float y;
    asm("cvt.rna.tf32.f32 %0, %1;" : "=f"(y) : "f"(x));
    return y;
}
__device__ __forceinline__ uint32_t fbits(float f) { return __float_as_uint(f); }
__device__ __forceinline__ uint32_t smem_u32(const void* p) {
    uint32_t a;
    asm("{ .reg .u64 t; cvta.to.shared.u64 t, %1; cvt.u32.u64 %0, t; }" : "=r"(a) : "l"(p));
    return a;
}
// Async 16B copy gmem->smem (portable sm_80+; SASS LDGSTS)
__device__ __forceinline__ void cp16(uint32_t dst, const void* src) {
    asm volatile("cp.async.cg.shared.global [%0], [%1], 16;" :: "r"(dst), "l"(src));
}
#define CP_COMMIT() asm volatile("cp.async.commit_group;" ::: "memory")
#define CP_WAIT(N)  asm volatile("cp.async.wait_group %0;" :: "n"(N) : "memory")

// Portable warp MMA: D(16x8,f32) += A(16x8,tf32 row) * B(8x8,tf32 col)
__device__ __forceinline__ void mma_tf32(float* d, const uint32_t* a, const uint32_t* b) {
    asm volatile(
        "mma.sync.aligned.m16n8k8.row.col.f32.tf32.tf32.f32 "
        "{%0,%1,%2,%3}, {%4,%5,%6,%7}, {%8,%9}, {%0,%1,%2,%3};"
        : "+f"(d[0]), "+f"(d[1]), "+f"(d[2]), "+f"(d[3])
        : "r"(a[0]), "r"(a[1]), "r"(a[2]), "r"(a[3]), "r"(b[0]), "r"(b[1]));
}

// ---------------------------------------------------------------------------
// Prep: round x to tf32 (rna) once, so qkv can stream it via cp.async.
// ---------------------------------------------------------------------------
__global__ __launch_bounds__(256) void round_x(const float* __restrict__ x)
{
    size_t i = ((size_t)blockIdx.x * 256 + threadIdx.x) * 4;
    float4 v = *reinterpret_cast<const float4*>(x + i);
    v.x = to_tf32(v.x); v.y = to_tf32(v.y); v.z = to_tf32(v.z); v.w = to_tf32(v.w);
    *reinterpret_cast<float4*>(g_xr + i) = v;
}

// ---------------------------------------------------------------------------
// Weight transpose: g_wt[w][n][k] = tf32(W[k][n]).  Tiled 32x32.
// ---------------------------------------------------------------------------
__global__ void transpose_w(const float* __restrict__ Wq,
                            const float* __restrict__ Wk,
                            const float* __restrict__ Wv)
{
    __shared__ float tile[32][33];
    const float* W = (blockIdx.z == 0) ? Wq : (blockIdx.z == 1) ? Wk : Wv;
    float* Out = g_wt + (size_t)blockIdx.z * CCH * HH;
    const int k0 = blockIdx.x * 32, n0 = blockIdx.y * 32;
    const int tx = threadIdx.x, ty = threadIdx.y;
    #pragma unroll
    for (int i = 0; i < 4; i++)
        tile[ty + 8 * i][tx] = W[(size_t)(k0 + ty + 8 * i) * HH + (n0 + tx)];
    __syncthreads();
    #pragma unroll
    for (int i = 0; i < 4; i++)
        Out[(size_t)(n0 + ty + 8 * i) * CCH + (k0 + tx)] = to_tf32(tile[tx][ty + 8 * i]);
}

// ---------------------------------------------------------------------------
// QKV projection via mma.sync tf32 + cp.async double-buffered K-chunks.
// CTA tile: 128m x 128n, K chunks of 32 (24 chunks, 2 smem stages).
// 8 warps as 4m x 2n; warp tile 32x64. occ 2 via launch_bounds(256,2).
// ---------------------------------------------------------------------------
constexpr int XSTR = 36;               // smem row stride; conflict-free frag loads
constexpr int STG = 2 * 128 * XSTR;    // floats per stage (X tile + W tile)
constexpr int QKV_SMEM = 2 * STG * (int)sizeof(float);   // 73728 B
constexpr int NCH = CCH / 32;          // 24

__device__ __forceinline__ void qkv_load_chunk(
    uint32_t uS, int st, int c, const float* __restrict__ xr,
    const float* __restrict__ wt, int bm0, int bn0, int tid)
{
    const int k0 = c * 32;
    const uint32_t baseX = uS + (uint32_t)(st * STG) * 4u;
    const uint32_t baseW = baseX + (uint32_t)(128 * XSTR) * 4u;
    #pragma unroll
    for (int i = 0; i < 4; i++) {
        int e = tid + 256 * i;
        int r = e >> 3, k4 = (e & 7) * 4;
        cp16(baseX + (uint32_t)(r * XSTR + k4) * 4u, &xr[(size_t)(bm0 + r) * CCH + k0 + k4]);
    }
    #pragma unroll
    for (int i = 0; i < 4; i++) {
        int e = tid + 256 * i;
        int r = e >> 3, k4 = (e & 7) * 4;
        cp16(baseW + (uint32_t)(r * XSTR + k4) * 4u, &wt[(size_t)(bn0 + r) * CCH + k0 + k4]);
    }
}

__global__ __launch_bounds__(256, 2) void qkv_mma()
{
    extern __shared__ float qsm[];
    const uint32_t uS = smem_u32(qsm);

    const int tid = threadIdx.x;
    const int w = tid >> 5, lane = tid & 31;
    const int gid = lane >> 2, tig = lane & 3;
    const int wm = w & 3, wn = w >> 2;
    const int bm0 = blockIdx.x * 128, bn0 = blockIdx.y * 128;
    const int wsel = blockIdx.z;
    const float* wt = g_wt + (size_t)wsel * CCH * HH;

    float acc[2][8][4];
    #pragma unroll
    for (int mf = 0; mf < 2; mf++)
        #pragma unroll
        for (int nf = 0; nf < 8; nf++)
            #pragma unroll
            for (int j = 0; j < 4; j++) acc[mf][nf][j] = 0.f;

    qkv_load_chunk(uS, 0, 0, g_xr, wt, bm0, bn0, tid);
    CP_COMMIT();

    for (int c = 0; c < NCH; c++) {
        if (c + 1 < NCH) {
            qkv_load_chunk(uS, (c + 1) & 1, c + 1, g_xr, wt, bm0, bn0, tid);
            CP_COMMIT();
            CP_WAIT(1);   // chunk c landed (c+1 may still fly)
        } else {
            CP_WAIT(0);
        }
        __syncthreads();

        const float* Xs = qsm + (c & 1) * STG;
        const float* Ws = Xs + 128 * XSTR;

        #pragma unroll
        for (int ks = 0; ks < 4; ks++) {
            const int kb = 8 * ks;
            uint32_t a[2][4];
            #pragma unroll
            for (int mf = 0; mf < 2; mf++) {
                const int r0 = 32 * wm + 16 * mf + gid;
                a[mf][0] = fbits(Xs[r0 * XSTR + kb + tig]);
                a[mf][1] = fbits(Xs[(r0 + 8) * XSTR + kb + tig]);
                a[mf][2] = fbits(Xs[r0 * XSTR + kb + tig + 4]);
                a[mf][3] = fbits(Xs[(r0 + 8) * XSTR + kb + tig + 4]);
            }
            #pragma unroll
            for (int nf = 0; nf < 8; nf++) {
                const int nr = 64 * wn + 8 * nf + gid;
                uint32_t b[2] = { fbits(Ws[nr * XSTR + kb + tig]),
                                  fbits(Ws[nr * XSTR + kb + tig + 4]) };
                mma_tf32(acc[0][nf], a[0], b);
                mma_tf32(acc[1][nf], a[1], b);
            }
        }
        __syncthreads();   // all warps done with stage c before its re-fill
    }

    if (wsel < 2) {
        float* Out = (wsel == 0) ? g_q : g_k;
        #pragma unroll
        for (int mf = 0; mf < 2; mf++)
            #pragma unroll
            for (int nf = 0; nf < 8; nf++) {
                const int row = bm0 + 32 * wm + 16 * mf + gid;
                const int col = bn0 + 64 * wn + 8 * nf + 2 * tig;
                float2 v0 = make_float2(to_tf32(acc[mf][nf][0]), to_tf32(acc[mf][nf][1]));
                float2 v1 = make_float2(to_tf32(acc[mf][nf][2]), to_tf32(acc[mf][nf][3]));
                *reinterpret_cast<float2*>(&Out[(size_t)row * HH + col]) = v0;
                *reinterpret_cast<float2*>(&Out[(size_t)(row + 8) * HH + col]) = v1;
            }
    } else {
        #pragma unroll
        for (int mf = 0; mf < 2; mf++)
            #pragma unroll
            for (int nf = 0; nf < 8; nf++) {
                const int col = bn0 + 64 * wn + 8 * nf + 2 * tig;
                #pragma unroll
                for (int h = 0; h < 2; h++) {
                    const int m = bm0 + 32 * wm + 16 * mf + gid + 8 * h;
                    const int bb = m >> 11, t = m & 2047;
                    g_vt[((size_t)bb * HH + col) * TT + t]     = to_tf32(acc[mf][nf][2 * h]);
                    g_vt[((size_t)bb * HH + col + 1) * TT + t] = to_tf32(acc[mf][nf][2 * h + 1]);
                }
            }
    }
}

// ---------------------------------------------------------------------------
// Flash attention (causal) via mma.sync tf32 + cp.async pipelining.
// Balanced pairing: CTA p handles qt = 31-p then qt = p  ->  exactly 33
// tile-iters per CTA, 128 CTAs, one wave.
// ---------------------------------------------------------------------------
constexpr int QKS = 260;   // Q/K row stride: bank = 4*gid + tig, conflict-free
constexpr int VTS = 68;    // Vt/Ps row stride
constexpr int OFF_QS = 0;
constexpr int OFF_KS = OFF_QS + 64 * QKS;       // 16640
constexpr int OFF_VT = OFF_KS + 64 * QKS;       // 33280
constexpr int OFF_PS = OFF_VT + 256 * VTS;      // 50688
constexpr int OFF_PM = OFF_PS + 64 * VTS;       // 55040  (pm[2][64])
constexpr int OFF_S2 = OFF_PM + 128;            // 55168  (ps2[2][64])
constexpr int ATTN_SMEM = (OFF_S2 + 128) * (int)sizeof(float);   // 221184 B

__global__ __launch_bounds__(256) void attn_mma(float* __restrict__ out)
{
    extern __shared__ float sm[];
    float* Qs = sm + OFF_QS;
    float* Ks = sm + OFF_KS;
    float* Vt = sm + OFF_VT;
    float* Ps = sm + OFF_PS;
    float* pm = sm + OFF_PM;
    float* ps2 = sm + OFF_S2;

    const uint32_t sb = smem_u32(sm);
    const uint32_t uQs = sb + OFF_QS * 4, uKs = sb + OFF_KS * 4, uVt = sb + OFF_VT * 4;

    const int b = blockIdx.y;
    const int p = blockIdx.x;                     // 0..15
    const int tid = threadIdx.x;
    const int w = tid >> 5, lane = tid & 31;
    const int gid = lane >> 2, tig = lane & 3;
    const int wm = w & 3, wn = w >> 2;
    const int m0 = 16 * wm;
    const int r0 = m0 + gid, r1 = r0 + 8;
    const float scale = rsqrtf((float)CCH);

    #pragma unroll 1
    for (int ti = 0; ti < 2; ti++) {
        const int qt = (ti == 0) ? (TT / 64 - 1 - p) : p;   // heavy first

        CP_WAIT(0);        // drain prior tile's dangling prefetch
        __syncthreads();   // prior tile's smem readers done

        // Prologue: async-load Q tile and K(0).
        #pragma unroll
        for (int i = 0; i < 16; i++) {
            int e = tid + 256 * i;
            int r = e >> 6, d4 = (e & 63) * 4;
            cp16(uQs + (r * QKS + d4) * 4, &g_q[((size_t)b * TT + qt * 64 + r) * HH + d4]);
        }
        CP_COMMIT();
        #pragma unroll
        for (int i = 0; i < 16; i++) {
            int e = tid + 256 * i;
            int r = e >> 6, d4 = (e & 63) * 4;
            cp16(uKs + (r * QKS + d4) * 4, &g_k[((size_t)b * TT + r) * HH + d4]);
        }
        CP_COMMIT();

        float o[16][4];
        #pragma unroll
        for (int nf = 0; nf < 16; nf++)
            #pragma unroll
            for (int j = 0; j < 4; j++) o[nf][j] = 0.f;
        float m0r = -INFINITY, m1r = -INFINITY, l0r = 0.f, l1r = 0.f;

        for (int jt = 0; jt <= qt; jt++) {
            CP_WAIT(0);
            __syncthreads();

            // Issue V(jt) async — hidden behind S-mma + softmax.
            #pragma unroll
            for (int i = 0; i < 16; i++) {
                int e = tid + 256 * i;
                int d = e >> 4, k4 = (e & 15) * 4;
                cp16(uVt + (d * VTS + k4) * 4, &g_vt[((size_t)b * HH + d) * TT + jt * 64 + k4]);
            }
            CP_COMMIT();

            // ---- S = Q K^T (warp tile 16 x 32) ----
            float sacc[4][4];
            #pragma unroll
            for (int nf = 0; nf < 4; nf++)
                #pragma unroll
                for (int j = 0; j < 4; j++) sacc[nf][j] = 0.f;

            const int n0s = 32 * wn;
            #pragma unroll 4
            for (int ks = 0; ks < 32; ks++) {
                const int kb = 8 * ks;
                uint32_t a[4];
                a[0] = fbits(Qs[r0 * QKS + kb + tig]);
                a[1] = fbits(Qs[r1 * QKS + kb + tig]);
                a[2] = fbits(Qs[r0 * QKS + kb + tig + 4]);
                a[3] = fbits(Qs[r1 * QKS + kb + tig + 4]);
                #pragma unroll
                for (int nf = 0; nf < 4; nf++) {
                    const int nr = n0s + 8 * nf + gid;
                    uint32_t bb[2] = { fbits(Ks[nr * QKS + kb + tig]),
                                       fbits(Ks[nr * QKS + kb + tig + 4]) };
                    mma_tf32(sacc[nf], a, bb);
                }
            }

            // ---- register softmax: scale, mask, partial row max ----
            const bool dtile = (jt == qt);
            float mx0 = -INFINITY, mx1 = -INFINITY;
            #pragma unroll
            for (int nf = 0; nf < 4; nf++) {
                const int c0 = n0s + 8 * nf + 2 * tig;
                float v00 = sacc[nf][0] * scale, v01 = sacc[nf][1] * scale;
                float v10 = sacc[nf][2] * scale, v11 = sacc[nf][3] * scale;
                if (dtile) {
                    if (c0 > r0)     v00 = -INFINITY;
                    if (c0 + 1 > r0) v01 = -INFINITY;
                    if (c0 > r1)     v10 = -INFINITY;
                    if (c0 + 1 > r1) v11 = -INFINITY;
                }
                sacc[nf][0] = v00; sacc[nf][1] = v01; sacc[nf][2] = v10; sacc[nf][3] = v11;
                mx0 = fmaxf(mx0, fmaxf(v00, v01));
                mx1 = fmaxf(mx1, fmaxf(v10, v11));
            }
            mx0 = fmaxf(mx0, __shfl_xor_sync(0xffffffffu, mx0, 1));
            mx0 = fmaxf(mx0, __shfl_xor_sync(0xffffffffu, mx0, 2));
            mx1 = fmaxf(mx1, __shfl_xor_sync(0xffffffffu, mx1, 1));
            mx1 = fmaxf(mx1, __shfl_xor_sync(0xffffffffu, mx1, 2));
            if (tig == 0) { pm[wn * 64 + r0] = mx0; pm[wn * 64 + r1] = mx1; }
            __syncthreads();   // pm visible; Ks reads done

            // Prefetch K(jt+1) — hidden behind exp + PV.
            {
                const int jn = (jt < qt) ? jt + 1 : jt;
                #pragma unroll
                for (int i = 0; i < 16; i++) {
                    int e = tid + 256 * i;
                    int r = e >> 6, d4 = (e & 63) * 4;
                    cp16(uKs + (r * QKS + d4) * 4,
                         &g_k[((size_t)b * TT + jn * 64 + r) * HH + d4]);
                }
                CP_COMMIT();
            }

            // ---- combine max, exp, partial sums, write P ----
            const float nm0 = fmaxf(m0r, fmaxf(pm[r0], pm[64 + r0]));
            const float nm1 = fmaxf(m1r, fmaxf(pm[r1], pm[64 + r1]));
            const float cr0 = __expf(m0r - nm0);
            const float cr1 = __expf(m1r - nm1);
            m0r = nm0; m1r = nm1;

            float s0 = 0.f, s1 = 0.f;
            #pragma unroll
            for (int nf = 0; nf < 4; nf++) {
                const int c0 = n0s + 8 * nf + 2 * tig;
                float p00 = __expf(sacc[nf][0] - nm0);
                float p01 = __expf(sacc[nf][1] - nm0);
                float p10 = __expf(sacc[nf][2] - nm1);
                float p11 = __expf(sacc[nf][3] - nm1);
                s0 += p00 + p01;
                s1 += p10 + p11;
                *reinterpret_cast<float2*>(&Ps[r0 * VTS + c0]) =
                    make_float2(to_tf32(p00), to_tf32(p01));
                *reinterpret_cast<float2*>(&Ps[r1 * VTS + c0]) =
                    make_float2(to_tf32(p10), to_tf32(p11));
            }
            s0 += __shfl_xor_sync(0xffffffffu, s0, 1);
            s0 += __shfl_xor_sync(0xffffffffu, s0, 2);
            s1 += __shfl_xor_sync(0xffffffffu, s1, 1);
            s1 += __shfl_xor_sync(0xffffffffu, s1, 2);
            if (tig == 0) { ps2[wn * 64 + r0] = s0; ps2[wn * 64 + r1] = s1; }

            CP_WAIT(1);        // V(jt) landed (K prefetch may still fly)
            __syncthreads();   // Ps/ps2 visible; V visible

            l0r = l0r * cr0 + ps2[r0] + ps2[64 + r0];
            l1r = l1r * cr1 + ps2[r1] + ps2[64 + r1];

            // ---- rescale O, then O += P V (warp tile 16 x 128) ----
            #pragma unroll
            for (int nf = 0; nf < 16; nf++) {
                o[nf][0] *= cr0; o[nf][1] *= cr0;
                o[nf][2] *= cr1; o[nf][3] *= cr1;
            }
            const int n0o = 128 * wn;
            #pragma unroll
            for (int ks = 0; ks < 8; ks++) {
                const int kb = 8 * ks;
                uint32_t a[4];
                a[0] = fbits(Ps[r0 * VTS + kb + tig]);
                a[1] = fbits(Ps[r1 * VTS + kb + tig]);
                a[2] = fbits(Ps[r0 * VTS + kb + tig + 4]);
                a[3] = fbits(Ps[r1 * VTS + kb + tig + 4]);
                #pragma unroll
                for (int nf = 0; nf < 16; nf++) {
                    const int nr = n0o + 8 * nf + gid;
                    uint32_t bb[2] = { fbits(Vt[nr * VTS + kb + tig]),
                                       fbits(Vt[nr * VTS + kb + tig + 4]) };
                    mma_tf32(o[nf], a, bb);
                }
            }
        }

        // Normalize and write out this tile.
        const float i0 = 1.f / l0r, i1 = 1.f / l1r;
        const int n0o = 128 * wn;
        #pragma unroll
        for (int nf = 0; nf < 16; nf++) {
            const int row = qt * 64 + r0;
            const int col = n0o + 8 * nf + 2 * tig;
            const size_t b0 = ((size_t)b * TT + row) * HH + col;
            const size_t b1 = ((size_t)b * TT + row + 8) * HH + col;
            *reinterpret_cast<float2*>(&out[b0]) = make_float2(o[nf][0] * i0, o[nf][1] * i0);
            *reinterpret_cast<float2*>(&out[b1]) = make_float2(o[nf][2] * i1, o[nf][3] * i1);
        }
    }
    CP_WAIT(0);   // drain dangling prefetch before exit
}

extern "C" void kernel_launch(void* const* d_in, const int* in_sizes, int n_in,
                              void* d_out, int out_size)
{
    const float* x  = (const float*)d_in[0];
    const float* Wq = (const float*)d_in[1];
    const float* Wk = (const float*)d_in[2];
    const float* Wv = (const float*)d_in[3];
    float* out = (float*)d_out;

    cudaFuncSetAttribute(qkv_mma, cudaFuncAttributeMaxDynamicSharedMemorySize, QKV_SMEM);
    cudaFuncSetAttribute(attn_mma, cudaFuncAttributeMaxDynamicSharedMemorySize, ATTN_SMEM);

    round_x<<<M_TOT * CCH / 4 / 256, 256>>>(x);
    transpose_w<<<dim3(CCH / 32, HH / 32, 3), dim3(32, 8)>>>(Wq, Wk, Wv);
    qkv_mma<<<dim3(M_TOT / 128, HH / 128, 3), 256, QKV_SMEM>>>();
    attn_mma<<<dim3(16, 8), 256, ATTN_SMEM>>>(out);
}

// round 14
// speedup vs baseline: 5.2148x; 1.0118x over previous
#include <cuda_runtime.h>
#include <math.h>
#include <cstdint>

// Problem constants
constexpr int BB = 8;
constexpr int TT = 2048;
constexpr int CCH = 768;   // n_embed
constexpr int HH = 256;    // head_size
constexpr int M_TOT = BB * TT;  // 16384

// k-dim permutation within 16-float groups: position p holds original col
// c = 4*(p&3) + (p>>2), so a float4 at words [4g+t] = cols {t, t+4, t+8, t+12}
// of group g — exactly the mma fragment k-pattern for TWO k8-steps.
#define PERM16(c) (((c) & ~15) | (((c) & 3) << 2) | (((c) >> 2) & 3))

// Device-global scratch (no allocation allowed).
__device__ float g_xr[M_TOT * CCH];          // x, tf32, k-dim perm16
__device__ float g_q[M_TOT * HH];            // [m][n], tf32, head-dim perm16
__device__ float g_k[M_TOT * HH];            // [m][n], tf32, head-dim perm16
__device__ float g_vt[BB * HH * TT];         // [b][n][t], tf32, t-dim perm16
__device__ float g_wt[3 * HH * CCH];         // [w][n][k], tf32, k-dim perm16

__device__ __forceinline__ float to_tf32(float x) {
    float y;
    asm("cvt.rna.tf32.f32 %0, %1;" : "=f"(y) : "f"(x));
    return y;
}
__device__ __forceinline__ uint32_t fbits(float f) { return __float_as_uint(f); }
__device__ __forceinline__ uint32_t smem_u32(const void* p) {
    uint32_t a;
    asm("{ .reg .u64 t; cvta.to.shared.u64 t, %1; cvt.u32.u64 %0, t; }" : "=r"(a) : "l"(p));
    return a;
}
__device__ __forceinline__ void cp16(uint32_t dst, const void* src) {
    asm volatile("cp.async.cg.shared.global [%0], [%1], 16;" :: "r"(dst), "l"(src));
}
#define CP_COMMIT() asm volatile("cp.async.commit_group;" ::: "memory")
#define CP_WAIT(N)  asm volatile("cp.async.wait_group %0;" :: "n"(N) : "memory")

// Portable warp MMA: D(16x8,f32) += A(16x8,tf32 row) * B(8x8,tf32 col)
__device__ __forceinline__ void mma_tf32(float* d, const uint32_t* a, const uint32_t* b) {
    asm volatile(
        "mma.sync.aligned.m16n8k8.row.col.f32.tf32.tf32.f32 "
        "{%0,%1,%2,%3}, {%4,%5,%6,%7}, {%8,%9}, {%0,%1,%2,%3};"
        : "+f"(d[0]), "+f"(d[1]), "+f"(d[2]), "+f"(d[3])
        : "r"(a[0]), "r"(a[1]), "r"(a[2]), "r"(a[3]), "r"(b[0]), "r"(b[1]));
}

// ---------------------------------------------------------------------------
// Prep: round x to tf32 and permute k-dim (gather 4 strided, write float4).
// ---------------------------------------------------------------------------
__global__ __launch_bounds__(256) void round_x(const float* __restrict__ x)
{
    size_t w = (size_t)blockIdx.x * 256 + threadIdx.x;   // output float4 word
    size_t base = (w >> 2) << 4;                          // 16-float group base
    int t = (int)(w & 3);
    float4 v;
    v.x = to_tf32(x[base + t]);
    v.y = to_tf32(x[base + 4 + t]);
    v.z = to_tf32(x[base + 8 + t]);
    v.w = to_tf32(x[base + 12 + t]);
    reinterpret_cast<float4*>(g_xr)[w] = v;
}

// ---------------------------------------------------------------------------
// Weight transpose: g_wt[w][n][perm16(k)] = tf32(W[k][n]).  Tiled 32x32.
// ---------------------------------------------------------------------------
__global__ void transpose_w(const float* __restrict__ Wq,
                            const float* __restrict__ Wk,
                            const float* __restrict__ Wv)
{
    __shared__ float tile[32][33];
    const float* W = (blockIdx.z == 0) ? Wq : (blockIdx.z == 1) ? Wk : Wv;
    float* Out = g_wt + (size_t)blockIdx.z * CCH * HH;
    const int k0 = blockIdx.x * 32, n0 = blockIdx.y * 32;
    const int tx = threadIdx.x, ty = threadIdx.y;
    #pragma unroll
    for (int i = 0; i < 4; i++)
        tile[ty + 8 * i][tx] = W[(size_t)(k0 + ty + 8 * i) * HH + (n0 + tx)];
    __syncthreads();
    const int kp = PERM16(k0 + tx);
    #pragma unroll
    for (int i = 0; i < 4; i++)
        Out[(size_t)(n0 + ty + 8 * i) * CCH + kp] = to_tf32(tile[tx][ty + 8 * i]);
}

// ---------------------------------------------------------------------------
// QKV projection via mma.sync tf32 + cp.async double-buffered K-chunks.
// CTA tile: 128m x 128n, K chunks of 32 (24 chunks, 2 smem stages).
// Fragments via LDS.128 from perm16 k-layout + XOR swizzle (no padding).
// ---------------------------------------------------------------------------
constexpr int STG = 2 * 128 * 32;      // floats per stage (X tile + W tile)
constexpr int QKV_SMEM = 2 * STG * (int)sizeof(float);   // 65536 B
constexpr int NCH = CCH / 32;          // 24

__device__ __forceinline__ void qkv_load_chunk(
    uint32_t uS, int st, int c, const float* __restrict__ xr,
    const float* __restrict__ wt, int bm0, int bn0, int tid)
{
    const int k0 = c * 32;
    const uint32_t baseX = uS + (uint32_t)(st * STG) * 4u;
    const uint32_t baseW = baseX + (uint32_t)(128 * 32) * 4u;
    #pragma unroll
    for (int i = 0; i < 4; i++) {
        int e = tid + 256 * i;
        int r = e >> 3, w = e & 7;
        int wd = w ^ ((r & 1) << 2);
        cp16(baseX + (uint32_t)(r * 32 + 4 * wd) * 4u, &xr[(size_t)(bm0 + r) * CCH + k0 + 4 * w]);
    }
    #pragma unroll
    for (int i = 0; i < 4; i++) {
        int e = tid + 256 * i;
        int r = e >> 3, w = e & 7;
        int wd = w ^ ((r & 1) << 2);
        cp16(baseW + (uint32_t)(r * 32 + 4 * wd) * 4u, &wt[(size_t)(bn0 + r) * CCH + k0 + 4 * w]);
    }
}

__global__ __launch_bounds__(256, 2) void qkv_mma()
{
    extern __shared__ float qsm[];
    const uint32_t uS = smem_u32(qsm);

    const int tid = threadIdx.x;
    const int w = tid >> 5, lane = tid & 31;
    const int gid = lane >> 2, tig = lane & 3;
    const int sw = (gid & 1) << 2;     // row-parity swizzle (all frag rows ≡ gid mod 2)
    const int wm = w & 3, wn = w >> 2;
    const int bm0 = blockIdx.x * 128, bn0 = blockIdx.y * 128;
    const int wsel = blockIdx.z;
    const float* wt = g_wt + (size_t)wsel * CCH * HH;

    float acc[2][8][4];
    #pragma unroll
    for (int mf = 0; mf < 2; mf++)
        #pragma unroll
        for (int nf = 0; nf < 8; nf++)
            #pragma unroll
            for (int j = 0; j < 4; j++) acc[mf][nf][j] = 0.f;

    qkv_load_chunk(uS, 0, 0, g_xr, wt, bm0, bn0, tid);
    CP_COMMIT();

    for (int c = 0; c < NCH; c++) {
        if (c + 1 < NCH) {
            qkv_load_chunk(uS, (c + 1) & 1, c + 1, g_xr, wt, bm0, bn0, tid);
            CP_COMMIT();
            CP_WAIT(1);
        } else {
            CP_WAIT(0);
        }
        __syncthreads();

        const float4* Xs4 = reinterpret_cast<const float4*>(qsm + (c & 1) * STG);
        const float4* Ws4 = Xs4 + 128 * 8;

        #pragma unroll
        for (int g = 0; g < 2; g++) {
            const int wq = (4 * g + tig) ^ sw;
            uint32_t aE[2][4], aO[2][4];   // ks even / odd per mf
            #pragma unroll
            for (int mf = 0; mf < 2; mf++) {
                const int r0 = 32 * wm + 16 * mf + gid;
                float4 x0 = Xs4[r0 * 8 + wq];
                float4 x1 = Xs4[(r0 + 8) * 8 + wq];
                aE[mf][0] = fbits(x0.x); aE[mf][1] = fbits(x1.x);
                aE[mf][2] = fbits(x0.y); aE[mf][3] = fbits(x1.y);
                aO[mf][0] = fbits(x0.z); aO[mf][1] = fbits(x1.z);
                aO[mf][2] = fbits(x0.w); aO[mf][3] = fbits(x1.w);
            }
            #pragma unroll
            for (int nf = 0; nf < 8; nf++) {
                const int nr = 64 * wn + 8 * nf + gid;
                float4 wb = Ws4[nr * 8 + wq];
                uint32_t b0[2] = { fbits(wb.x), fbits(wb.y) };
                uint32_t b1[2] = { fbits(wb.z), fbits(wb.w) };
                mma_tf32(acc[0][nf], aE[0], b0);
                mma_tf32(acc[1][nf], aE[1], b0);
                mma_tf32(acc[0][nf], aO[0], b1);
                mma_tf32(acc[1][nf], aO[1], b1);
            }
        }
        __syncthreads();
    }

    if (wsel < 2) {
        float* Out = (wsel == 0) ? g_q : g_k;
        #pragma unroll
        for (int mf = 0; mf < 2; mf++)
            #pragma unroll
            for (int nf = 0; nf < 8; nf++) {
                const int row = bm0 + 32 * wm + 16 * mf + gid;
                const int col = bn0 + 64 * wn + 8 * nf + 2 * tig;
                const int c0p = PERM16(col), c1p = PERM16(col + 1);
                Out[(size_t)row * HH + c0p]       = to_tf32(acc[mf][nf][0]);
                Out[(size_t)row * HH + c1p]       = to_tf32(acc[mf][nf][1]);
                Out[(size_t)(row + 8) * HH + c0p] = to_tf32(acc[mf][nf][2]);
                Out[(size_t)(row + 8) * HH + c1p] = to_tf32(acc[mf][nf][3]);
            }
    } else {
        #pragma unroll
        for (int mf = 0; mf < 2; mf++)
            #pragma unroll
            for (int nf = 0; nf < 8; nf++) {
                const int col = bn0 + 64 * wn + 8 * nf + 2 * tig;
                #pragma unroll
                for (int h = 0; h < 2; h++) {
                    const int m = bm0 + 32 * wm + 16 * mf + gid + 8 * h;
                    const int bb = m >> 11, t = m & 2047;
                    const int tp = PERM16(t);
                    g_vt[((size_t)bb * HH + col) * TT + tp]     = to_tf32(acc[mf][nf][2 * h]);
                    g_vt[((size_t)bb * HH + col + 1) * TT + tp] = to_tf32(acc[mf][nf][2 * h + 1]);
                }
            }
    }
}

// ---------------------------------------------------------------------------
// Flash attention (causal) via mma.sync tf32 + cp.async pipelining.
// Balanced pairing: CTA p does qt = 31-p then qt = p (33 iters each, 1 wave).
// All fragment feeds via LDS.128 from perm16 layouts + XOR swizzle.
// Smem (exact, no padding): Qs/Ks 64x256, Vt 256x64, Ps 64x64.
// ---------------------------------------------------------------------------
constexpr int OFF_QS = 0;
constexpr int OFF_KS = OFF_QS + 64 * 256;   // 16384
constexpr int OFF_VT = OFF_KS + 64 * 256;   // 32768
constexpr int OFF_PS = OFF_VT + 256 * 64;   // 49152
constexpr int OFF_PM = OFF_PS + 64 * 64;    // 53248  (pm[2][64])
constexpr int OFF_S2 = OFF_PM + 128;        // 53376  (ps2[2][64])
constexpr int ATTN_SMEM = (OFF_S2 + 128) * (int)sizeof(float);   // 214016 B

__global__ __launch_bounds__(256) void attn_mma(float* __restrict__ out)
{
    extern __shared__ float sm[];
    float* Ps = sm + OFF_PS;
    float* pm = sm + OFF_PM;
    float* ps2 = sm + OFF_S2;
    const float4* Qs4 = reinterpret_cast<const float4*>(sm + OFF_QS);
    const float4* Ks4 = reinterpret_cast<const float4*>(sm + OFF_KS);
    const float4* Vt4 = reinterpret_cast<const float4*>(sm + OFF_VT);
    const float4* Ps4 = reinterpret_cast<const float4*>(Ps);

    const uint32_t sb = smem_u32(sm);
    const uint32_t uQs = sb + OFF_QS * 4, uKs = sb + OFF_KS * 4, uVt = sb + OFF_VT * 4;

    const int b = blockIdx.y;
    const int p = blockIdx.x;                     // 0..15
    const int tid = threadIdx.x;
    const int w = tid >> 5, lane = tid & 31;
    const int gid = lane >> 2, tig = lane & 3;
    const int sw = (gid & 1) << 2;                // row-parity swizzle
    const int wm = w & 3, wn = w >> 2;
    const int m0 = 16 * wm;
    const int r0 = m0 + gid, r1 = r0 + 8;
    const float scale = rsqrtf((float)CCH);

    #pragma unroll 1
    for (int ti = 0; ti < 2; ti++) {
        const int qt = (ti == 0) ? (TT / 64 - 1 - p) : p;   // heavy first

        CP_WAIT(0);
        __syncthreads();

        // Prologue: async-load Q tile and K(0) (swizzled dst).
        #pragma unroll
        for (int i = 0; i < 16; i++) {
            int e = tid + 256 * i;
            int r = e >> 6, wq = e & 63;
            int wd = wq ^ ((r & 1) << 2);
            cp16(uQs + (uint32_t)(r * 256 + 4 * wd) * 4u,
                 &g_q[((size_t)b * TT + qt * 64 + r) * HH + 4 * wq]);
        }
        CP_COMMIT();
        #pragma unroll
        for (int i = 0; i < 16; i++) {
            int e = tid + 256 * i;
            int r = e >> 6, wq = e & 63;
            int wd = wq ^ ((r & 1) << 2);
            cp16(uKs + (uint32_t)(r * 256 + 4 * wd) * 4u,
                 &g_k[((size_t)b * TT + r) * HH + 4 * wq]);
        }
        CP_COMMIT();

        float o[16][4];
        #pragma unroll
        for (int nf = 0; nf < 16; nf++)
            #pragma unroll
            for (int j = 0; j < 4; j++) o[nf][j] = 0.f;
        float m0r = -INFINITY, m1r = -INFINITY, l0r = 0.f, l1r = 0.f;

        for (int jt = 0; jt <= qt; jt++) {
            CP_WAIT(0);
            __syncthreads();

            // Issue V(jt) async — hidden behind S-mma + softmax.
            #pragma unroll
            for (int i = 0; i < 16; i++) {
                int e = tid + 256 * i;
                int d = e >> 4, wq = e & 15;
                int wd = wq ^ ((d & 1) << 2);
                cp16(uVt + (uint32_t)(d * 64 + 4 * wd) * 4u,
                     &g_vt[((size_t)b * HH + d) * TT + jt * 64 + 4 * wq]);
            }
            CP_COMMIT();

            // ---- S = Q K^T (warp tile 16 x 32), LDS.128 feeds 2 k-steps ----
            float sacc[4][4];
            #pragma unroll
            for (int nf = 0; nf < 4; nf++)
                #pragma unroll
                for (int j = 0; j < 4; j++) sacc[nf][j] = 0.f;

            const int n0s = 32 * wn;
            #pragma unroll 4
            for (int g = 0; g < 16; g++) {
                const int wq = (4 * g + tig) ^ sw;
                float4 q0 = Qs4[r0 * 64 + wq];
                float4 q1 = Qs4[r1 * 64 + wq];
                uint32_t aE[4] = { fbits(q0.x), fbits(q1.x), fbits(q0.y), fbits(q1.y) };
                uint32_t aO[4] = { fbits(q0.z), fbits(q1.z), fbits(q0.w), fbits(q1.w) };
                #pragma unroll
                for (int nf = 0; nf < 4; nf++) {
                    const int nr = n0s + 8 * nf + gid;
                    float4 kb = Ks4[nr * 64 + wq];
                    uint32_t b0[2] = { fbits(kb.x), fbits(kb.y) };
                    uint32_t b1[2] = { fbits(kb.z), fbits(kb.w) };
                    mma_tf32(sacc[nf], aE, b0);
                    mma_tf32(sacc[nf], aO, b1);
                }
            }

            // ---- register softmax: scale, mask, partial row max ----
            const bool dtile = (jt == qt);
            float mx0 = -INFINITY, mx1 = -INFINITY;
            #pragma unroll
            for (int nf = 0; nf < 4; nf++) {
                const int c0 = n0s + 8 * nf + 2 * tig;
                float v00 = sacc[nf][0] * scale, v01 = sacc[nf][1] * scale;
                float v10 = sacc[nf][2] * scale, v11 = sacc[nf][3] * scale;
                if (dtile) {
                    if (c0 > r0)     v00 = -INFINITY;
                    if (c0 + 1 > r0) v01 = -INFINITY;
                    if (c0 > r1)     v10 = -INFINITY;
                    if (c0 + 1 > r1) v11 = -INFINITY;
                }
                sacc[nf][0] = v00; sacc[nf][1] = v01; sacc[nf][2] = v10; sacc[nf][3] = v11;
                mx0 = fmaxf(mx0, fmaxf(v00, v01));
                mx1 = fmaxf(mx1, fmaxf(v10, v11));
            }
            mx0 = fmaxf(mx0, __shfl_xor_sync(0xffffffffu, mx0, 1));
            mx0 = fmaxf(mx0, __shfl_xor_sync(0xffffffffu, mx0, 2));
            mx1 = fmaxf(mx1, __shfl_xor_sync(0xffffffffu, mx1, 1));
            mx1 = fmaxf(mx1, __shfl_xor_sync(0xffffffffu, mx1, 2));
            if (tig == 0) { pm[wn * 64 + r0] = mx0; pm[wn * 64 + r1] = mx1; }
            __syncthreads();   // pm visible; Ks reads done

            // Prefetch K(jt+1) — hidden behind exp + PV.
            {
                const int jn = (jt < qt) ? jt + 1 : jt;
                #pragma unroll
                for (int i = 0; i < 16; i++) {
                    int e = tid + 256 * i;
                    int r = e >> 6, wq = e & 63;
                    int wd = wq ^ ((r & 1) << 2);
                    cp16(uKs + (uint32_t)(r * 256 + 4 * wd) * 4u,
                         &g_k[((size_t)b * TT + jn * 64 + r) * HH + 4 * wq]);
                }
                CP_COMMIT();
            }

            // ---- combine max, exp, partial sums, write P (perm16+swizzle) ----
            const float nm0 = fmaxf(m0r, fmaxf(pm[r0], pm[64 + r0]));
            const float nm1 = fmaxf(m1r, fmaxf(pm[r1], pm[64 + r1]));
            const float cr0 = __expf(m0r - nm0);
            const float cr1 = __expf(m1r - nm1);
            m0r = nm0; m1r = nm1;

            float s0 = 0.f, s1 = 0.f;
            #pragma unroll
            for (int nf = 0; nf < 4; nf++) {
                const int c0 = n0s + 8 * nf + 2 * tig;
                float p00 = __expf(sacc[nf][0] - nm0);
                float p01 = __expf(sacc[nf][1] - nm0);
                float p10 = __expf(sacc[nf][2] - nm1);
                float p11 = __expf(sacc[nf][3] - nm1);
                s0 += p00 + p01;
                s1 += p10 + p11;
                const int q0p = PERM16(c0), q1p = PERM16(c0 + 1);
                const int i0s = 4 * ((q0p >> 2) ^ sw) + (q0p & 3);
                const int i1s = 4 * ((q1p >> 2) ^ sw) + (q1p & 3);
                Ps[r0 * 64 + i0s] = to_tf32(p00);
                Ps[r0 * 64 + i1s] = to_tf32(p01);
                Ps[r1 * 64 + i0s] = to_tf32(p10);
                Ps[r1 * 64 + i1s] = to_tf32(p11);
            }
            s0 += __shfl_xor_sync(0xffffffffu, s0, 1);
            s0 += __shfl_xor_sync(0xffffffffu, s0, 2);
            s1 += __shfl_xor_sync(0xffffffffu, s1, 1);
            s1 += __shfl_xor_sync(0xffffffffu, s1, 2);
            if (tig == 0) { ps2[wn * 64 + r0] = s0; ps2[wn * 64 + r1] = s1; }

            CP_WAIT(1);        // V(jt) landed (K prefetch may still fly)
            __syncthreads();   // Ps/ps2 visible; V visible

            l0r = l0r * cr0 + ps2[r0] + ps2[64 + r0];
            l1r = l1r * cr1 + ps2[r1] + ps2[64 + r1];

            // ---- rescale O, then O += P V (warp tile 16 x 128) ----
            #pragma unroll
            for (int nf = 0; nf < 16; nf++) {
                o[nf][0] *= cr0; o[nf][1] *= cr0;
                o[nf][2] *= cr1; o[nf][3] *= cr1;
            }
            const int n0o = 128 * wn;
            #pragma unroll
            for (int g = 0; g < 4; g++) {
                const int wq = (4 * g + tig) ^ sw;
                float4 p0 = Ps4[r0 * 16 + wq];
                float4 p1 = Ps4[r1 * 16 + wq];
                uint32_t aE[4] = { fbits(p0.x), fbits(p1.x), fbits(p0.y), fbits(p1.y) };
                uint32_t aO[4] = { fbits(p0.z), fbits(p1.z), fbits(p0.w), fbits(p1.w) };
                #pragma unroll
                for (int nf = 0; nf < 16; nf++) {
                    const int nr = n0o + 8 * nf + gid;
                    float4 vb = Vt4[nr * 16 + wq];
                    uint32_t b0[2] = { fbits(vb.x), fbits(vb.y) };
                    uint32_t b1[2] = { fbits(vb.z), fbits(vb.w) };
                    mma_tf32(o[nf], aE, b0);
                    mma_tf32(o[nf], aO, b1);
                }
            }
        }

        // Normalize and write out this tile.
        const float i0 = 1.f / l0r, i1 = 1.f / l1r;
        const int n0o = 128 * wn;
        #pragma unroll
        for (int nf = 0; nf < 16; nf++) {
            const int row = qt * 64 + r0;
            const int col = n0o + 8 * nf + 2 * tig;
            const size_t b0 = ((size_t)b * TT + row) * HH + col;
            const size_t b1 = ((size_t)b * TT + row + 8) * HH + col;
            *reinterpret_cast<float2*>(&out[b0]) = make_float2(o[nf][0] * i0, o[nf][1] * i0);
            *reinterpret_cast<float2*>(&out[b1]) = make_float2(o[nf][2] * i1, o[nf][3] * i1);
        }
    }
    CP_WAIT(0);   // drain dangling prefetch before exit
}

extern "C" void kernel_launch(void* const* d_in, const int* in_sizes, int n_in,
                              void* d_out, int out_size)
{
    const float* x  = (const float*)d_in[0];
    const float* Wq = (const float*)d_in[1];
    const float* Wk = (const float*)d_in[2];
    const float* Wv = (const float*)d_in[3];
    float* out = (float*)d_out;

    cudaFuncSetAttribute(qkv_mma, cudaFuncAttributeMaxDynamicSharedMemorySize, QKV_SMEM);
    cudaFuncSetAttribute(attn_mma, cudaFuncAttributeMaxDynamicSharedMemorySize, ATTN_SMEM);

    round_x<<<M_TOT * CCH / 4 / 256, 256>>>(x);
    transpose_w<<<dim3(CCH / 32, HH / 32, 3), dim3(32, 8)>>>(Wq, Wk, Wv);
    qkv_mma<<<dim3(M_TOT / 128, HH / 128, 3), 256, QKV_SMEM>>>();
    attn_mma<<<dim3(16, 8), 256, ATTN_SMEM>>>(out);
}